// round 15
// baseline (speedup 1.0000x reference)
#include <cuda_runtime.h>
#include <cstdint>
#include <math.h>

#define NN 8192
#define EPSF 1e-20f
#define NITER 32
#define NCTA 148
#define NTHR 512
#define ROWB 16384               // bytes per int16 H row
#define RDEPTH 8                 // TMA ring slots (power of 2)

// dynamic smem layout
#define SM_MBAR 0                // 8 mbarriers, 16B stride (ends 128)
#define SM_WRED 128              // 2 x 16 warp partials, double-buffered, 16B aligned
#define SM_GPART 1024            // 512 floats (phase-B group partials + reduce scratch)
#define SM_SRED 3072             // 64 floats (phase-B rs partials)
#define SM_T    3328             // 64 floats: this CTA's t_r = (Hp)_row
#define SM_QH   3584             // 64 floats: incremental q_hat for own rows
#define SM_P    3840             // 56 floats: p on own columns (for phaseB)
#define SM_SC   4096             // 64 floats: per-row quant scales
#define SM_RING 4352             // RDEPTH x 16384 row buffers
#define SMEM_TOTAL (SM_RING + RDEPTH * ROWB)

// ---- device scratch (no allocations allowed) ----
__device__ short g_Hq[(size_t)NN * NN];    // 134 MB int16 quantized H
__device__ float g_rowscale[NN];           // per-row scale (maxabs/32767)
__device__ float g_slab[NCTA * NN];        // per-CTA Ap partial slabs
__device__ float g_ttpart[NCTA];
__device__ float g_rspart[NCTA];
__device__ float g_r[NN], g_v[NN], g_qh[NN];
__device__ float g_msum[8];
__device__ float g_fftsum[8];
__device__ unsigned g_flags[NCTA];         // grid-barrier flags (monotone)

// ---------------- PTX helpers ----------------
__device__ __forceinline__ uint32_t sm_u32(const void* p) {
    uint32_t a;
    asm("{ .reg .u64 t; cvta.to.shared.u64 t, %1; cvt.u32.u64 %0, t; }" : "=r"(a) : "l"(p));
    return a;
}
#define MB_INIT(a, c) \
    asm volatile("mbarrier.init.shared.b64 [%0], %1;" :: "r"(a), "r"(c) : "memory")
#define MB_EXPECT(a, b) \
    asm volatile("mbarrier.arrive.expect_tx.shared.b64 _, [%0], %1;" :: "r"(a), "r"(b) : "memory")
#define BULK_LD(dst, src, sz, mb) \
    asm volatile("cp.async.bulk.shared::cta.global.mbarrier::complete_tx::bytes [%0], [%1], %2, [%3];" \
                 :: "r"(dst), "l"(src), "r"(sz), "r"(mb) : "memory")

__device__ __forceinline__ void mb_wait(uint32_t mbar, uint32_t parity) {
    uint32_t done;
    do {
        asm volatile("{ .reg .pred p; mbarrier.try_wait.parity.acquire.cta.shared::cta.b64 p, [%1], %2; "
                     "selp.b32 %0, 1, 0, p; }" : "=r"(done) : "r"(mbar), "r"(parity) : "memory");
    } while (!done);
}

__device__ __forceinline__ void grid_bar(int tid, int bid, unsigned gen) {
    __syncthreads();
    if (tid == 0)
        asm volatile("st.global.release.gpu.u32 [%0], %1;" :: "l"(&g_flags[bid]), "r"(gen) : "memory");
    if (tid < NCTA) {
        unsigned v;
        do {
            asm volatile("ld.global.acquire.gpu.u32 %0, [%1];" : "=r"(v) : "l"(&g_flags[tid]) : "memory");
        } while ((int)(v - gen) < 0);
    }
    __syncthreads();
}

// deterministic 512-thread sum (fixed tree), result broadcast
__device__ __forceinline__ float block_sum512(float v, float* scr, int tid) {
    for (int o = 16; o; o >>= 1) v += __shfl_xor_sync(0xffffffffu, v, o);
    if ((tid & 31) == 0) scr[tid >> 5] = v;
    __syncthreads();
    if (tid < 16) {
        float w = scr[tid];
        for (int o = 8; o; o >>= 1) w += __shfl_xor_sync(0xffffu, w, o);
        if (tid == 0) scr[0] = w;
    }
    __syncthreads();
    float s = scr[0];
    __syncthreads();
    return s;
}

// dot of 16 packed int16 (two uint4) against pf[16]
__device__ __forceinline__ float dot16(uint4 a0, uint4 a1, const float* pf) {
    const short* s0 = (const short*)&a0;
    const short* s1 = (const short*)&a1;
    float d = 0.f;
#pragma unroll
    for (int e = 0; e < 8; e++) d += (float)s0[e] * pf[e];
#pragma unroll
    for (int e = 0; e < 8; e++) d += (float)s1[e] * pf[8 + e];
    return d;
}
// apa += coef * row (16 packed int16)
__device__ __forceinline__ void axpy16(uint4 a0, uint4 a1, float coef, float* ap) {
    const short* s0 = (const short*)&a0;
    const short* s1 = (const short*)&a1;
#pragma unroll
    for (int e = 0; e < 8; e++) ap[e] += coef * (float)s0[e];
#pragma unroll
    for (int e = 0; e < 8; e++) ap[8 + e] += coef * (float)s1[e];
}

// ---------------------------------------------------------------------------
// fp32 H -> int16 per-row quantization. One block per row, 256 threads.
// ---------------------------------------------------------------------------
__global__ __launch_bounds__(256) void quant_h_kernel(const float* __restrict__ H) {
    __shared__ float red[256];
    int row = blockIdx.x;
    int tid = threadIdx.x;
    const float4* h4 = (const float4*)(H + (size_t)row * NN);
    float4 loc[8];
    float m = 0.f;
#pragma unroll
    for (int k = 0; k < 4; k++) {
        int o = tid + 256 * k;
        float4 a = h4[2 * o];
        float4 b = h4[2 * o + 1];
        loc[2 * k] = a;
        loc[2 * k + 1] = b;
        m = fmaxf(m, fmaxf(fmaxf(fabsf(a.x), fabsf(a.y)), fmaxf(fabsf(a.z), fabsf(a.w))));
        m = fmaxf(m, fmaxf(fmaxf(fabsf(b.x), fabsf(b.y)), fmaxf(fabsf(b.z), fabsf(b.w))));
    }
    red[tid] = m;
    __syncthreads();
    for (int s = 128; s > 0; s >>= 1) {
        if (tid < s) red[tid] = fmaxf(red[tid], red[tid + s]);
        __syncthreads();
    }
    float maxab = fmaxf(red[0], 1e-30f);
    float inv = 32767.0f / maxab;
    if (tid == 0) g_rowscale[row] = maxab / 32767.0f;
    uint4* dst = (uint4*)g_Hq + (size_t)row * 1024;
#pragma unroll
    for (int k = 0; k < 4; k++) {
        int o = tid + 256 * k;
        float f[8] = { loc[2*k].x, loc[2*k].y, loc[2*k].z, loc[2*k].w,
                       loc[2*k+1].x, loc[2*k+1].y, loc[2*k+1].z, loc[2*k+1].w };
        int q[8];
#pragma unroll
        for (int e = 0; e < 8; e++) {
            int v = __float2int_rn(f[e] * inv);
            q[e] = max(-32767, min(32767, v));
        }
        uint4 o4;
        o4.x = (unsigned)(unsigned short)(short)q[0] | ((unsigned)(unsigned short)(short)q[1] << 16);
        o4.y = (unsigned)(unsigned short)(short)q[2] | ((unsigned)(unsigned short)(short)q[3] << 16);
        o4.z = (unsigned)(unsigned short)(short)q[4] | ((unsigned)(unsigned short)(short)q[5] << 16);
        o4.w = (unsigned)(unsigned short)(short)q[6] | ((unsigned)(unsigned short)(short)q[7] << 16);
        dst[o] = o4;
    }
}

// helper: tid0 issues the TMA load for logical row index u (slot u&7)
__device__ __forceinline__ void issue_row(uint32_t smb, int row0, unsigned u) {
    uint32_t slot = u & (RDEPTH - 1);
    uint32_t mb = smb + SM_MBAR + slot * 16;
    MB_EXPECT(mb, ROWB);
    BULK_LD(smb + SM_RING + slot * ROWB,
            (const void*)(g_Hq + (size_t)(row0 + (int)u % 8192) * 0 +    /* dummy avoid */
                          (size_t)0), (uint32_t)ROWB, mb);
}

// ---------------------------------------------------------------------------
// Matvec pass (MODE 0), compute-pipelined: row r's reduce-consume overlaps
// row r+1's load+dot.  wred double-buffered; one __syncthreads per row.
// Setup pass (MODE 1) stays simple single-row.
// ---------------------------------------------------------------------------
template<int MODE>
__device__ __forceinline__ float run_pass(char* smem, uint32_t smb, int tid,
                                          int row0, int nrows, unsigned& gq,
                                          const float* pf, float* apaf,
                                          const float* __restrict__ xvec,
                                          const float* scsm,
                                          bool pre_done, bool pre_next) {
    float* wred = (float*)(smem + SM_WRED);
    float* smt  = (float*)(smem + SM_T);
    const short* Hb = g_Hq;
#pragma unroll
    for (int i = 0; i < 16; i++) apaf[i] = 0.f;
    float ta = 0.f;
    if (!pre_done && tid == 0) {
        for (int k = 0; k < RDEPTH; k++) {
            unsigned u = gq + k;
            uint32_t slot = u & (RDEPTH - 1);
            uint32_t mb = smb + SM_MBAR + slot * 16;
            MB_EXPECT(mb, ROWB);
            BULK_LD(smb + SM_RING + slot * ROWB,
                    (const void*)(Hb + (size_t)(row0 + k) * NN), (uint32_t)ROWB, mb);
        }
    }
    if (MODE == 1) {
        for (int r = 0; r < nrows; r++) {
            unsigned u = gq + r;
            uint32_t slot = u & (RDEPTH - 1);
            mb_wait(smb + SM_MBAR + slot * 16, (u >> 3) & 1);
            const uint4* rowu = (const uint4*)(smem + SM_RING + slot * ROWB);
            uint4 a0 = rowu[tid], a1 = rowu[tid + 512];
            float coef = xvec[row0 + r] * scsm[r];
            __syncthreads();
            if (tid == 0 && r + RDEPTH < nrows) {
                uint32_t mb = smb + SM_MBAR + slot * 16;
                MB_EXPECT(mb, ROWB);
                BULK_LD(smb + SM_RING + slot * ROWB,
                        (const void*)(Hb + (size_t)(row0 + r + RDEPTH) * NN), (uint32_t)ROWB, mb);
            }
            axpy16(a0, a1, coef, apaf);
        }
    } else {
        // ---- prologue: row 0 load + dot ----
        uint4 c0r, c1r;                       // current row raw (consumed this iter)
        {
            unsigned u = gq;
            uint32_t slot = u & (RDEPTH - 1);
            mb_wait(smb + SM_MBAR + slot * 16, (u >> 3) & 1);
            const uint4* rowu = (const uint4*)(smem + SM_RING + slot * ROWB);
            c0r = rowu[tid]; c1r = rowu[tid + 512];
            float d = dot16(c0r, c1r, pf);
            for (int o = 16; o; o >>= 1) d += __shfl_xor_sync(0xffffffffu, d, o);
            if ((tid & 31) == 0) wred[tid >> 5] = d;   // buffer 0
        }
        for (int r = 0; r < nrows; r++) {
            __syncthreads();                 // publishes wred[r&1]; retires row r's smem reads
            unsigned u = gq + r;
            uint32_t slot = u & (RDEPTH - 1);
            if (tid == 0 && r + RDEPTH < nrows) {      // refill slot r with row r+RDEPTH
                uint32_t mb = smb + SM_MBAR + slot * 16;
                MB_EXPECT(mb, ROWB);
                BULK_LD(smb + SM_RING + slot * ROWB,
                        (const void*)(Hb + (size_t)(row0 + r + RDEPTH) * NN), (uint32_t)ROWB, mb);
            }
            // load + dot row r+1 (writes the OTHER wred buffer)
            uint4 n0r, n1r;
            if (r + 1 < nrows) {
                unsigned un = u + 1;
                uint32_t sn = un & (RDEPTH - 1);
                mb_wait(smb + SM_MBAR + sn * 16, (un >> 3) & 1);
                const uint4* rowu = (const uint4*)(smem + SM_RING + sn * ROWB);
                n0r = rowu[tid]; n1r = rowu[tid + 512];
                float d = dot16(n0r, n1r, pf);
                for (int o = 16; o; o >>= 1) d += __shfl_xor_sync(0xffffffffu, d, o);
                if ((tid & 31) == 0) wred[((r + 1) & 1) * 16 + (tid >> 5)] = d;
            }
            // consume row r (reduce published by this iteration's barrier)
            {
                const float4* w4 = (const float4*)(wred + (r & 1) * 16);
                float4 s0 = w4[0], s1 = w4[1], s2 = w4[2], s3 = w4[3];
                float traw = ((s0.x + s0.y) + (s0.z + s0.w))
                           + ((s1.x + s1.y) + (s1.z + s1.w))
                           + ((s2.x + s2.y) + (s2.z + s2.w))
                           + ((s3.x + s3.y) + (s3.z + s3.w));
                float sr = scsm[r];
                float tr = traw * sr;
                if (tid == 0) smt[r] = tr;
                ta += tr * tr;
                axpy16(c0r, c1r, tr * sr, apaf);
            }
            if (r + 1 < nrows) { c0r = n0r; c1r = n1r; }
        }
    }
    gq += (unsigned)nrows;
    if (pre_next && tid == 0) {
        for (int k = 0; k < RDEPTH; k++) {
            unsigned u = gq + k;
            uint32_t slot = u & (RDEPTH - 1);
            uint32_t mb = smb + SM_MBAR + slot * 16;
            MB_EXPECT(mb, ROWB);
            BULK_LD(smb + SM_RING + slot * ROWB,
                    (const void*)(Hb + (size_t)(row0 + k) * NN), (uint32_t)ROWB, mb);
        }
    }
    return ta;
}

// write apaf (16 cols per thread) to this CTA's slab
__device__ __forceinline__ void slab_store(int bid, int tid, const float* apaf) {
    float4* slab4 = (float4*)(g_slab + (size_t)bid * NN);
    const float4* a4 = (const float4*)apaf;
    slab4[2 * tid]        = a4[0];
    slab4[2 * tid + 1]    = a4[1];
    slab4[2 * tid + 1024] = a4[2];
    slab4[2 * tid + 1025] = a4[3];
}

// phase B: slab reduce over own columns + vector update (or setup init)
__device__ __forceinline__ void phaseB(char* smem, int tid, int bid, int c0, int nc,
                                       float alpha, bool setup) {
    float* sgp = (float*)(smem + SM_GPART);
    float* sred = (float*)(smem + SM_SRED);
    float* psm = (float*)(smem + SM_P);
    int g = tid >> 6, tc = tid & 63;
    float part = 0.f;
    if (tc < nc) {
#pragma unroll 4
        for (int cs = g; cs < NCTA; cs += 8) part += g_slab[(size_t)cs * NN + c0 + tc];
    }
    sgp[g * 64 + tc] = part;
    __syncthreads();
    if (tid < nc) {
        float ap = 0.f;
#pragma unroll
        for (int gg = 0; gg < 8; gg++) ap += sgp[gg * 64 + tid];
        int j = c0 + tid;
        float rn;
        if (setup) {
            g_v[j] = 0.f;
            g_r[j] = ap;      // r = b
            rn = ap;
        } else {
            g_v[j] += alpha * psm[tid];
            rn = g_r[j] - alpha * ap;
            g_r[j] = rn;
        }
        sred[tid] = rn * rn;
    }
    __syncthreads();
    if (tid == 0) {
        float s = 0.f;
        for (int i = 0; i < nc; i++) s += sred[i];
        g_rspart[bid] = s;
    }
}

// ---------------------------------------------------------------------------
// Persistent CG kernel: setup + 32 iterations; q_hat accumulated in smem.
// ---------------------------------------------------------------------------
__global__ void __launch_bounds__(NTHR, 1) cgm_persistent(const float* __restrict__ x) {
    extern __shared__ char smem[];
    int tid = threadIdx.x, bid = blockIdx.x;
    uint32_t smb = sm_u32(smem);
    float* smt = (float*)(smem + SM_T);
    float* smqh = (float*)(smem + SM_QH);
    float* psm = (float*)(smem + SM_P);
    float* scsm = (float*)(smem + SM_SC);
    float* scr = (float*)(smem + SM_GPART);
    if (tid == 0) {
        for (int s = 0; s < RDEPTH; s++) MB_INIT(smb + SM_MBAR + s * 16, 1);
    }
    if (tid < 64) smqh[tid] = 0.f;

    int row0, nrows;
    if (bid < 52) { row0 = bid * 56; nrows = 56; }
    else          { row0 = 2912 + (bid - 52) * 55; nrows = 55; }
    int c0 = row0, nc = nrows;

    if (tid < nrows) scsm[tid] = g_rowscale[row0 + tid];
    __syncthreads();
    unsigned base_gen = g_flags[bid];
    unsigned barn = 0;
    unsigned gq = 0;

    float apaf[16], pfv[16];
    float rs = 0.f;

    // ---- setup: b = H^T x, then r=b, v=0, rs0 partials ----
    run_pass<1>(smem, smb, tid, row0, nrows, gq, pfv, apaf, x, scsm, false, true);
    slab_store(bid, tid, apaf);
    grid_bar(tid, bid, base_gen + (++barn));
    phaseB(smem, tid, bid, c0, nc, 0.f, true);
    grid_bar(tid, bid, base_gen + (++barn));

    const int fidx[4] = { 2 * tid, 2 * tid + 1, 2 * tid + 1024, 2 * tid + 1025 };

    for (int it = 0; it < NITER; it++) {
        // ---- A: beta (parallel reduce), p update (regs + own-col smem) ----
        float rsv = (tid < NCTA) ? g_rspart[tid] : 0.f;
        float rs_new = block_sum512(rsv, scr, tid);
        float beta = (it == 0) ? 0.f : rs_new / (rs + EPSF);
        rs = rs_new;
#pragma unroll
        for (int c = 0; c < 4; c++) {
            float4 rr = ((const float4*)g_r)[fidx[c]];
            float4 pv;
            if (it == 0) pv = rr;
            else pv = make_float4(rr.x + beta * pfv[4 * c],     rr.y + beta * pfv[4 * c + 1],
                                  rr.z + beta * pfv[4 * c + 2], rr.w + beta * pfv[4 * c + 3]);
            pfv[4 * c] = pv.x; pfv[4 * c + 1] = pv.y;
            pfv[4 * c + 2] = pv.z; pfv[4 * c + 3] = pv.w;
            int col0 = 4 * fidx[c];
            if (col0 + 3 >= c0 && col0 < c0 + nc) {
#pragma unroll
                for (int e = 0; e < 4; e++) {
                    int jj = col0 + e;
                    if (jj >= c0 && jj < c0 + nc) psm[jj - c0] = pfv[4 * c + e];
                }
            }
        }
        // ---- matvec: slab partials of H^T(Hp), tt partials, smem t ----
        float ta = run_pass<0>(smem, smb, tid, row0, nrows, gq, pfv, apaf, nullptr,
                               scsm, true, it < NITER - 1);
        slab_store(bid, tid, apaf);
        if (tid == 0) g_ttpart[bid] = ta;
        grid_bar(tid, bid, base_gen + (++barn));

        // ---- B: alpha (parallel reduce), qh += alpha*t, Ap reduce + v,r + rs ----
        float ttv = (tid < NCTA) ? g_ttpart[tid] : 0.f;
        float tt = block_sum512(ttv, scr, tid);
        float alpha = rs / (tt + EPSF);
        if (tid < nrows) smqh[tid] += alpha * smt[tid];
        __syncthreads();                 // scr reuse in phaseB
        phaseB(smem, tid, bid, c0, nc, alpha, false);
        grid_bar(tid, bid, base_gen + (++barn));
    }

    if (tid < nrows) g_qh[row0 + tid] = smqh[tid];
}

// ---------------------------------------------------------------------------
// Fused tail kernel 1: blocks 0-3 = FFT modes; block 4 = time-domain metrics.
// ---------------------------------------------------------------------------
__global__ void __launch_bounds__(1024) metrics_fft_kernel(const float* __restrict__ x,
                                                           const float* __restrict__ qt,
                                                           const float* __restrict__ vt) {
    int tid = threadIdx.x;
    if (blockIdx.x == 4) {
        float acc[7] = {0.f, 0.f, 0.f, 0.f, 0.f, 0.f, 0.f};
        for (int j = tid; j < NN; j += 1024) {
            float qh = g_qh[j], vv = g_v[j];
            float qtj = qt[j], vtj = vt[j];
            float d0 = qh - x[j];
            float d1 = qh - qtj;
            float d2 = vv - vtj;
            acc[0] += d0 * d0;
            acc[1] += fabsf(d1);
            acc[2] += d1 * d1;
            acc[3] += qtj * qtj;
            acc[4] += fabsf(d2);
            acc[5] += d2 * d2;
            acc[6] += vtj * vtj;
        }
        __shared__ float red[1024];
#pragma unroll
        for (int s = 0; s < 7; s++) {
            red[tid] = acc[s];
            __syncthreads();
            for (int o = 512; o > 0; o >>= 1) {
                if (tid < o) red[tid] += red[tid + o];
                __syncthreads();
            }
            if (tid == 0) g_msum[s] = red[0];
            __syncthreads();
        }
        return;
    }

    __shared__ float2 Z[4096];
    __shared__ float red[1024];
    int mode = blockIdx.x;

    for (int n = tid; n < 4096; n += 1024) {
        int i0 = 2 * n, i1 = 2 * n + 1;
        float a, b;
        if (mode == 0)      { a = g_qh[i0] - qt[i0]; b = g_qh[i1] - qt[i1]; }
        else if (mode == 1) { a = qt[i0];            b = qt[i1]; }
        else if (mode == 2) { a = g_v[i0] - vt[i0];  b = g_v[i1] - vt[i1]; }
        else                { a = vt[i0];            b = vt[i1]; }
        int r = (int)(__brev((unsigned)n) >> 20);
        Z[r] = make_float2(a, b);
    }
    __syncthreads();

    for (int half = 1; half < 4096; half <<= 1) {
        for (int i = tid; i < 2048; i += 1024) {
            int pos = i & (half - 1);
            int idx1 = ((i ^ pos) << 1) | pos;
            int idx2 = idx1 + half;
            float s, c;
            sincospif((float)pos / (float)half, &s, &c);
            float2 z2 = Z[idx2];
            float2 t = make_float2(c * z2.x + s * z2.y, c * z2.y - s * z2.x);
            float2 z1 = Z[idx1];
            Z[idx2] = make_float2(z1.x - t.x, z1.y - t.y);
            Z[idx1] = make_float2(z1.x + t.x, z1.y + t.y);
        }
        __syncthreads();
    }

    float sabs = 0.f, ssq = 0.f;
    for (int k = tid; k <= 4096; k += 1024) {
        float2 Zk = Z[k & 4095];
        float2 Zm = Z[(4096 - k) & 4095];
        float2 Zmc = make_float2(Zm.x, -Zm.y);
        float2 Fe = make_float2(0.5f * (Zk.x + Zmc.x), 0.5f * (Zk.y + Zmc.y));
        float2 Fd = make_float2(Zk.x - Zmc.x, Zk.y - Zmc.y);
        float2 Fo = make_float2(0.5f * Fd.y, -0.5f * Fd.x);
        float s, c;
        sincospif((float)k / 4096.0f, &s, &c);
        float Xr = Fe.x + (c * Fo.x + s * Fo.y);
        float Xi = Fe.y + (c * Fo.y - s * Fo.x);
        float m2 = Xr * Xr + Xi * Xi;
        sabs += sqrtf(m2);
        ssq += m2;
    }
    red[tid] = sabs;
    __syncthreads();
    for (int s = 512; s > 0; s >>= 1) {
        if (tid < s) red[tid] += red[tid + s];
        __syncthreads();
    }
    if (tid == 0) g_fftsum[2 * mode] = red[0];
    __syncthreads();
    red[tid] = ssq;
    __syncthreads();
    for (int s = 512; s > 0; s >>= 1) {
        if (tid < s) red[tid] += red[tid + s];
        __syncthreads();
    }
    if (tid == 0) g_fftsum[2 * mode + 1] = red[0];
}

// ---------------------------------------------------------------------------
// Fused tail kernel 2: copy v (all blocks) + scalars (block 0 / thread 0).
// ---------------------------------------------------------------------------
__global__ void finalize_out_kernel(float* __restrict__ out, int out_size) {
    int j = blockIdx.x * 128 + threadIdx.x;
    if (j < out_size) {
        if (j < NN) out[j] = g_v[j];
        else if (j >= NN + 11) out[j] = 0.f;
    }
    if (blockIdx.x == 0 && threadIdx.x == 0) {
        float res[11];
        res[0]  = sqrtf(g_msum[0]);
        res[1]  = g_msum[1] / (float)NN;
        res[2]  = g_msum[2] / (g_msum[3] + EPSF);
        res[3]  = g_msum[4] / (float)NN;
        res[4]  = g_msum[5] / (g_msum[6] + EPSF);
        res[5]  = g_msum[2] / (float)NN;
        res[6]  = g_msum[5] / (float)NN;
        res[7]  = g_fftsum[0] / 4097.0f;
        res[8]  = g_fftsum[1] / (g_fftsum[3] + EPSF);
        res[9]  = g_fftsum[4] / 4097.0f;
        res[10] = g_fftsum[5] / (g_fftsum[7] + EPSF);
        for (int k = 0; k < 11; k++)
            if (NN + k < out_size) out[NN + k] = res[k];
    }
}

extern "C" void kernel_launch(void* const* d_in, const int* in_sizes, int n_in,
                              void* d_out, int out_size) {
    const float* H = nullptr;
    const float* x = nullptr;
    const float* vt = nullptr;
    const float* qt = nullptr;
    int vecseen = 0;
    for (int i = 0; i < n_in; i++) {
        if (in_sizes[i] == NN * NN) {
            H = (const float*)d_in[i];
        } else if (in_sizes[i] == NN) {
            if (vecseen == 0)      x  = (const float*)d_in[i];
            else if (vecseen == 1) vt = (const float*)d_in[i];
            else if (vecseen == 2) qt = (const float*)d_in[i];
            vecseen++;
        }
    }
    float* out = (float*)d_out;

    cudaFuncSetAttribute(cgm_persistent, cudaFuncAttributeMaxDynamicSharedMemorySize,
                         SMEM_TOTAL);

    // fp32 H -> int16 per-row quantized copy (deterministic, each replay)
    quant_h_kernel<<<NN, 256>>>(H);

    cgm_persistent<<<NCTA, NTHR, SMEM_TOTAL>>>(x);
    metrics_fft_kernel<<<5, 1024>>>(x, qt, vt);
    {
        int nblk = (out_size + 127) / 128;
        if (nblk < 1) nblk = 1;
        finalize_out_kernel<<<nblk, 128>>>(out, out_size);
    }
}

// round 16
// speedup vs baseline: 1.1381x; 1.1381x over previous
#include <cuda_runtime.h>
#include <cstdint>
#include <math.h>

#define NN 8192
#define EPSF 1e-20f
#define NITER 32
#define NCTA 148
#define NSLAB (2 * NCTA)         // two row-group slabs per CTA
#define NTHR 512
#define ROWB 16384               // bytes per int16 H row
#define GDEPTH 4                 // ring slots per group (power of 2)

// dynamic smem layout
#define SM_MBAR 0                // 8 mbarriers (4 per group), 16B stride (ends 128)
#define SM_WRED 128              // per-group 2 x 8 warp partials: [grp*16 + buf*8 + w]
#define SM_GPART 1024            // 512 floats (phase-B group partials + reduce scratch)
#define SM_SRED 3072             // 64 floats (phase-B rs partials)
#define SM_T    3328             // 64 floats: this CTA's t_r = (Hp)_row
#define SM_QH   3584             // 64 floats: incremental q_hat for own rows
#define SM_P    3840             // 56 floats: p on own columns (for phaseB)
#define SM_SC   4096             // 64 floats: per-row quant scales
#define SM_RING 4352             // 8 x 16384 row buffers (slots: grp*4 + k)
#define SMEM_TOTAL (SM_RING + 8 * ROWB)

// ---- device scratch (no allocations allowed) ----
__device__ short g_Hq[(size_t)NN * NN];    // 134 MB int16 quantized H
__device__ float g_rowscale[NN];           // per-row scale (maxabs/32767)
__device__ float g_slab[(size_t)NSLAB * NN]; // 9.7 MB per-group Ap partial slabs
__device__ float g_ttpart[NSLAB];
__device__ float g_rspart[NCTA];
__device__ float g_r[NN], g_v[NN], g_qh[NN];
__device__ float g_msum[8];
__device__ float g_fftsum[8];
__device__ unsigned g_flags[NCTA];         // grid-barrier flags (monotone)

// ---------------- PTX helpers ----------------
__device__ __forceinline__ uint32_t sm_u32(const void* p) {
    uint32_t a;
    asm("{ .reg .u64 t; cvta.to.shared.u64 t, %1; cvt.u32.u64 %0, t; }" : "=r"(a) : "l"(p));
    return a;
}
#define MB_INIT(a, c) \
    asm volatile("mbarrier.init.shared.b64 [%0], %1;" :: "r"(a), "r"(c) : "memory")
#define MB_EXPECT(a, b) \
    asm volatile("mbarrier.arrive.expect_tx.shared.b64 _, [%0], %1;" :: "r"(a), "r"(b) : "memory")
#define BULK_LD(dst, src, sz, mb) \
    asm volatile("cp.async.bulk.shared::cta.global.mbarrier::complete_tx::bytes [%0], [%1], %2, [%3];" \
                 :: "r"(dst), "l"(src), "r"(sz), "r"(mb) : "memory")
#define GBAR(id) \
    asm volatile("bar.sync %0, 256;" :: "r"(id) : "memory")

__device__ __forceinline__ void mb_wait(uint32_t mbar, uint32_t parity) {
    uint32_t done;
    do {
        asm volatile("{ .reg .pred p; mbarrier.try_wait.parity.acquire.cta.shared::cta.b64 p, [%1], %2; "
                     "selp.b32 %0, 1, 0, p; }" : "=r"(done) : "r"(mbar), "r"(parity) : "memory");
    } while (!done);
}

__device__ __forceinline__ void grid_bar(int tid, int bid, unsigned gen) {
    __syncthreads();
    if (tid == 0)
        asm volatile("st.global.release.gpu.u32 [%0], %1;" :: "l"(&g_flags[bid]), "r"(gen) : "memory");
    if (tid < NCTA) {
        unsigned v;
        do {
            asm volatile("ld.global.acquire.gpu.u32 %0, [%1];" : "=r"(v) : "l"(&g_flags[tid]) : "memory");
        } while ((int)(v - gen) < 0);
    }
    __syncthreads();
}

// deterministic 512-thread sum (fixed tree), result broadcast
__device__ __forceinline__ float block_sum512(float v, float* scr, int tid) {
    for (int o = 16; o; o >>= 1) v += __shfl_xor_sync(0xffffffffu, v, o);
    if ((tid & 31) == 0) scr[tid >> 5] = v;
    __syncthreads();
    if (tid < 16) {
        float w = scr[tid];
        for (int o = 8; o; o >>= 1) w += __shfl_xor_sync(0xffffu, w, o);
        if (tid == 0) scr[0] = w;
    }
    __syncthreads();
    float s = scr[0];
    __syncthreads();
    return s;
}

// dot of 32 packed int16 (four uint4) against pf[32]
__device__ __forceinline__ float dot32(const uint4* a, const float* pf) {
    float d = 0.f;
#pragma unroll
    for (int c = 0; c < 4; c++) {
        const short* s = (const short*)&a[c];
#pragma unroll
        for (int e = 0; e < 8; e++) d += (float)s[e] * pf[8 * c + e];
    }
    return d;
}
// ap += coef * row (32 packed int16)
__device__ __forceinline__ void axpy32(const uint4* a, float coef, float* ap) {
#pragma unroll
    for (int c = 0; c < 4; c++) {
        const short* s = (const short*)&a[c];
#pragma unroll
        for (int e = 0; e < 8; e++) ap[8 * c + e] += coef * (float)s[e];
    }
}

// ---------------------------------------------------------------------------
// fp32 H -> int16 per-row quantization. One block per row, 256 threads.
// ---------------------------------------------------------------------------
__global__ __launch_bounds__(256) void quant_h_kernel(const float* __restrict__ H) {
    __shared__ float red[256];
    int row = blockIdx.x;
    int tid = threadIdx.x;
    const float4* h4 = (const float4*)(H + (size_t)row * NN);
    float4 loc[8];
    float m = 0.f;
#pragma unroll
    for (int k = 0; k < 4; k++) {
        int o = tid + 256 * k;
        float4 a = h4[2 * o];
        float4 b = h4[2 * o + 1];
        loc[2 * k] = a;
        loc[2 * k + 1] = b;
        m = fmaxf(m, fmaxf(fmaxf(fabsf(a.x), fabsf(a.y)), fmaxf(fabsf(a.z), fabsf(a.w))));
        m = fmaxf(m, fmaxf(fmaxf(fabsf(b.x), fabsf(b.y)), fmaxf(fabsf(b.z), fabsf(b.w))));
    }
    red[tid] = m;
    __syncthreads();
    for (int s = 128; s > 0; s >>= 1) {
        if (tid < s) red[tid] = fmaxf(red[tid], red[tid + s]);
        __syncthreads();
    }
    float maxab = fmaxf(red[0], 1e-30f);
    float inv = 32767.0f / maxab;
    if (tid == 0) g_rowscale[row] = maxab / 32767.0f;
    uint4* dst = (uint4*)g_Hq + (size_t)row * 1024;
#pragma unroll
    for (int k = 0; k < 4; k++) {
        int o = tid + 256 * k;
        float f[8] = { loc[2*k].x, loc[2*k].y, loc[2*k].z, loc[2*k].w,
                       loc[2*k+1].x, loc[2*k+1].y, loc[2*k+1].z, loc[2*k+1].w };
        int q[8];
#pragma unroll
        for (int e = 0; e < 8; e++) {
            int v = __float2int_rn(f[e] * inv);
            q[e] = max(-32767, min(32767, v));
        }
        uint4 o4;
        o4.x = (unsigned)(unsigned short)(short)q[0] | ((unsigned)(unsigned short)(short)q[1] << 16);
        o4.y = (unsigned)(unsigned short)(short)q[2] | ((unsigned)(unsigned short)(short)q[3] << 16);
        o4.z = (unsigned)(unsigned short)(short)q[4] | ((unsigned)(unsigned short)(short)q[5] << 16);
        o4.w = (unsigned)(unsigned short)(short)q[6] | ((unsigned)(unsigned short)(short)q[7] << 16);
        dst[o] = o4;
    }
}

// group leader: issue TMA load of global row grow into group slot (u & 3)
__device__ __forceinline__ void issue_g(uint32_t smb, int grp, unsigned u, int grow) {
    uint32_t slot = (uint32_t)grp * GDEPTH + (u & (GDEPTH - 1));
    uint32_t mb = smb + SM_MBAR + slot * 16;
    MB_EXPECT(mb, ROWB);
    BULK_LD(smb + SM_RING + slot * ROWB,
            (const void*)(g_Hq + (size_t)grow * NN), (uint32_t)ROWB, mb);
}

// ---------------------------------------------------------------------------
// Streaming pass, split into two independent 256-thread row groups.
// Group grp handles local rows lr = 2k+grp (global row0+lr), k = 0..nr2-1.
// Thread tg owns 32 columns: uint4 indices tg+256c, c=0..3.
// MODE 0: tr = s*rawdot -> apa += (tr*s)*row, ta += tr^2, smt[lr] = tr
// MODE 1: coef = x[row]*s -> apa += coef*row          (setup b = H^T x)
// pre_done/pre_next: cross-pass prefetch of each group's first GDEPTH rows.
// ---------------------------------------------------------------------------
template<int MODE>
__device__ __forceinline__ float run_pass(char* smem, uint32_t smb, int grp, int tg,
                                          int row0, int nr2, unsigned& uq,
                                          const float* pf, float* apaf,
                                          const float* __restrict__ xvec,
                                          const float* scsm,
                                          bool pre_done, bool pre_next) {
    float* wred = (float*)(smem + SM_WRED);
    float* smt  = (float*)(smem + SM_T);
#pragma unroll
    for (int i = 0; i < 32; i++) apaf[i] = 0.f;
    float ta = 0.f;
    if (!pre_done && tg == 0) {
        for (int k = 0; k < GDEPTH; k++)
            issue_g(smb, grp, uq + k, row0 + 2 * k + grp);
    }
    for (int k = 0; k < nr2; k++) {
        unsigned u = uq + k;
        uint32_t slot = (uint32_t)grp * GDEPTH + (u & (GDEPTH - 1));
        mb_wait(smb + SM_MBAR + slot * 16, (u >> 2) & 1);
        const uint4* rowu = (const uint4*)(smem + SM_RING + slot * ROWB);
        uint4 a[4];
#pragma unroll
        for (int c = 0; c < 4; c++) a[c] = rowu[tg + 256 * c];
        int lr = 2 * k + grp;
        float coef;
        if (MODE == 1) {
            coef = xvec[row0 + lr] * scsm[lr];
            GBAR(1 + grp);                 // group's LDS of this slot done
        } else {
            float d = dot32(a, pf);
            for (int o = 16; o; o >>= 1) d += __shfl_xor_sync(0xffffffffu, d, o);
            if ((tg & 31) == 0) wred[grp * 16 + (k & 1) * 8 + (tg >> 5)] = d;
            GBAR(1 + grp);
        }
        if (tg == 0 && k + GDEPTH < nr2)
            issue_g(smb, grp, u + GDEPTH, row0 + 2 * (k + GDEPTH) + grp);
        if (MODE == 0) {
            float traw = 0.f;
#pragma unroll
            for (int w = 0; w < 8; w++) traw += wred[grp * 16 + (k & 1) * 8 + w];
            float sr = scsm[lr];
            float tr = traw * sr;
            if (tg == 0) smt[lr] = tr;
            ta += tr * tr;
            coef = tr * sr;
        }
        axpy32(a, coef, apaf);
    }
    uq += (unsigned)nr2;
    if (pre_next && tg == 0) {
        for (int k = 0; k < GDEPTH; k++)
            issue_g(smb, grp, uq + k, row0 + 2 * k + grp);
    }
    return ta;
}

// write apaf (32 cols per thread) to this group's slab
__device__ __forceinline__ void slab_store(int sidx, int tg, const float* apaf) {
    float4* slab4 = (float4*)(g_slab + (size_t)sidx * NN);
    const float4* a4 = (const float4*)apaf;
#pragma unroll
    for (int c = 0; c < 4; c++) {
        slab4[512 * c + 2 * tg]     = a4[2 * c];
        slab4[512 * c + 2 * tg + 1] = a4[2 * c + 1];
    }
}

// phase B: slab reduce (296 slabs) over own columns + vector update
__device__ __forceinline__ void phaseB(char* smem, int tid, int bid, int c0, int nc,
                                       float alpha, bool setup) {
    float* sgp = (float*)(smem + SM_GPART);
    float* sred = (float*)(smem + SM_SRED);
    float* psm = (float*)(smem + SM_P);
    int g = tid >> 6, tc = tid & 63;
    float part = 0.f;
    if (tc < nc) {
#pragma unroll 4
        for (int cs = g; cs < NSLAB; cs += 8) part += g_slab[(size_t)cs * NN + c0 + tc];
    }
    sgp[g * 64 + tc] = part;
    __syncthreads();
    if (tid < nc) {
        float ap = 0.f;
#pragma unroll
        for (int gg = 0; gg < 8; gg++) ap += sgp[gg * 64 + tid];
        int j = c0 + tid;
        float rn;
        if (setup) {
            g_v[j] = 0.f;
            g_r[j] = ap;      // r = b
            rn = ap;
        } else {
            g_v[j] += alpha * psm[tid];
            rn = g_r[j] - alpha * ap;
            g_r[j] = rn;
        }
        sred[tid] = rn * rn;
    }
    __syncthreads();
    if (tid == 0) {
        float s = 0.f;
        for (int i = 0; i < nc; i++) s += sred[i];
        g_rspart[bid] = s;
    }
}

// ---------------------------------------------------------------------------
// Persistent CG kernel: setup + 32 iterations; q_hat accumulated in smem.
// ---------------------------------------------------------------------------
__global__ void __launch_bounds__(NTHR, 1) cgm_persistent(const float* __restrict__ x) {
    extern __shared__ char smem[];
    int tid = threadIdx.x, bid = blockIdx.x;
    int grp = tid >> 8, tg = tid & 255;
    uint32_t smb = sm_u32(smem);
    float* smt = (float*)(smem + SM_T);
    float* smqh = (float*)(smem + SM_QH);
    float* psm = (float*)(smem + SM_P);
    float* scsm = (float*)(smem + SM_SC);
    float* scr = (float*)(smem + SM_GPART);
    if (tid == 0) {
        for (int s = 0; s < 8; s++) MB_INIT(smb + SM_MBAR + s * 16, 1);
    }
    if (tid < 64) smqh[tid] = 0.f;

    // even row counts: 100 CTAs x 56 + 48 CTAs x 54 = 8192
    int row0, nrows;
    if (bid < 100) { row0 = bid * 56; nrows = 56; }
    else           { row0 = 5600 + (bid - 100) * 54; nrows = 54; }
    int nr2 = nrows >> 1;
    int c0 = row0, nc = nrows;
    int sidx = bid * 2 + grp;

    if (tid < nrows) scsm[tid] = g_rowscale[row0 + tid];
    __syncthreads();
    unsigned base_gen = g_flags[bid];
    unsigned barn = 0;
    unsigned uq = 0;

    float apaf[32], pfv[32];
    float rs = 0.f;

    // ---- setup: b = H^T x, then r=b, v=0, rs0 partials ----
    run_pass<1>(smem, smb, grp, tg, row0, nr2, uq, pfv, apaf, x, scsm, false, true);
    slab_store(sidx, tg, apaf);
    grid_bar(tid, bid, base_gen + (++barn));
    phaseB(smem, tid, bid, c0, nc, 0.f, true);
    grid_bar(tid, bid, base_gen + (++barn));

    for (int it = 0; it < NITER; it++) {
        // ---- A: beta (parallel reduce), p update (regs + own-col smem) ----
        float rsv = (tid < NCTA) ? g_rspart[tid] : 0.f;
        float rs_new = block_sum512(rsv, scr, tid);
        float beta = (it == 0) ? 0.f : rs_new / (rs + EPSF);
        rs = rs_new;
#pragma unroll
        for (int c = 0; c < 4; c++) {
            int f0 = 512 * c + 2 * tg;
            float4 rr0 = ((const float4*)g_r)[f0];
            float4 rr1 = ((const float4*)g_r)[f0 + 1];
            float rv[8] = { rr0.x, rr0.y, rr0.z, rr0.w, rr1.x, rr1.y, rr1.z, rr1.w };
#pragma unroll
            for (int e = 0; e < 8; e++) {
                float pv = (it == 0) ? rv[e] : rv[e] + beta * pfv[8 * c + e];
                pfv[8 * c + e] = pv;
            }
            int col0 = 2048 * c + 8 * tg;
            if (col0 + 7 >= c0 && col0 < c0 + nc) {
#pragma unroll
                for (int e = 0; e < 8; e++) {
                    int jj = col0 + e;
                    if (jj >= c0 && jj < c0 + nc) psm[jj - c0] = pfv[8 * c + e];
                }
            }
        }
        __syncthreads();   // pfv/psm ready before groups diverge into the pass
        // ---- matvec: group slab partials of H^T(Hp), tt partials, smem t ----
        float ta = run_pass<0>(smem, smb, grp, tg, row0, nr2, uq, pfv, apaf, nullptr,
                               scsm, true, it < NITER - 1);
        slab_store(sidx, tg, apaf);
        if (tg == 0) g_ttpart[sidx] = ta;
        grid_bar(tid, bid, base_gen + (++barn));

        // ---- B: alpha (parallel reduce), qh += alpha*t, Ap reduce + v,r + rs ----
        float ttv = (tid < NSLAB) ? g_ttpart[tid] : 0.f;
        float tt = block_sum512(ttv, scr, tid);
        float alpha = rs / (tt + EPSF);
        if (tid < nrows) smqh[tid] += alpha * smt[tid];
        __syncthreads();                 // scr reuse in phaseB
        phaseB(smem, tid, bid, c0, nc, alpha, false);
        grid_bar(tid, bid, base_gen + (++barn));
    }

    if (tid < nrows) g_qh[row0 + tid] = smqh[tid];
}

// ---------------------------------------------------------------------------
// Fused tail kernel 1: blocks 0-3 = FFT modes; block 4 = time-domain metrics.
// ---------------------------------------------------------------------------
__global__ void __launch_bounds__(1024) metrics_fft_kernel(const float* __restrict__ x,
                                                           const float* __restrict__ qt,
                                                           const float* __restrict__ vt) {
    int tid = threadIdx.x;
    if (blockIdx.x == 4) {
        float acc[7] = {0.f, 0.f, 0.f, 0.f, 0.f, 0.f, 0.f};
        for (int j = tid; j < NN; j += 1024) {
            float qh = g_qh[j], vv = g_v[j];
            float qtj = qt[j], vtj = vt[j];
            float d0 = qh - x[j];
            float d1 = qh - qtj;
            float d2 = vv - vtj;
            acc[0] += d0 * d0;
            acc[1] += fabsf(d1);
            acc[2] += d1 * d1;
            acc[3] += qtj * qtj;
            acc[4] += fabsf(d2);
            acc[5] += d2 * d2;
            acc[6] += vtj * vtj;
        }
        __shared__ float red[1024];
#pragma unroll
        for (int s = 0; s < 7; s++) {
            red[tid] = acc[s];
            __syncthreads();
            for (int o = 512; o > 0; o >>= 1) {
                if (tid < o) red[tid] += red[tid + o];
                __syncthreads();
            }
            if (tid == 0) g_msum[s] = red[0];
            __syncthreads();
        }
        return;
    }

    __shared__ float2 Z[4096];
    __shared__ float red[1024];
    int mode = blockIdx.x;

    for (int n = tid; n < 4096; n += 1024) {
        int i0 = 2 * n, i1 = 2 * n + 1;
        float a, b;
        if (mode == 0)      { a = g_qh[i0] - qt[i0]; b = g_qh[i1] - qt[i1]; }
        else if (mode == 1) { a = qt[i0];            b = qt[i1]; }
        else if (mode == 2) { a = g_v[i0] - vt[i0];  b = g_v[i1] - vt[i1]; }
        else                { a = vt[i0];            b = vt[i1]; }
        int r = (int)(__brev((unsigned)n) >> 20);
        Z[r] = make_float2(a, b);
    }
    __syncthreads();

    for (int half = 1; half < 4096; half <<= 1) {
        for (int i = tid; i < 2048; i += 1024) {
            int pos = i & (half - 1);
            int idx1 = ((i ^ pos) << 1) | pos;
            int idx2 = idx1 + half;
            float s, c;
            sincospif((float)pos / (float)half, &s, &c);
            float2 z2 = Z[idx2];
            float2 t = make_float2(c * z2.x + s * z2.y, c * z2.y - s * z2.x);
            float2 z1 = Z[idx1];
            Z[idx2] = make_float2(z1.x - t.x, z1.y - t.y);
            Z[idx1] = make_float2(z1.x + t.x, z1.y + t.y);
        }
        __syncthreads();
    }

    float sabs = 0.f, ssq = 0.f;
    for (int k = tid; k <= 4096; k += 1024) {
        float2 Zk = Z[k & 4095];
        float2 Zm = Z[(4096 - k) & 4095];
        float2 Zmc = make_float2(Zm.x, -Zm.y);
        float2 Fe = make_float2(0.5f * (Zk.x + Zmc.x), 0.5f * (Zk.y + Zmc.y));
        float2 Fd = make_float2(Zk.x - Zmc.x, Zk.y - Zmc.y);
        float2 Fo = make_float2(0.5f * Fd.y, -0.5f * Fd.x);
        float s, c;
        sincospif((float)k / 4096.0f, &s, &c);
        float Xr = Fe.x + (c * Fo.x + s * Fo.y);
        float Xi = Fe.y + (c * Fo.y - s * Fo.x);
        float m2 = Xr * Xr + Xi * Xi;
        sabs += sqrtf(m2);
        ssq += m2;
    }
    red[tid] = sabs;
    __syncthreads();
    for (int s = 512; s > 0; s >>= 1) {
        if (tid < s) red[tid] += red[tid + s];
        __syncthreads();
    }
    if (tid == 0) g_fftsum[2 * mode] = red[0];
    __syncthreads();
    red[tid] = ssq;
    __syncthreads();
    for (int s = 512; s > 0; s >>= 1) {
        if (tid < s) red[tid] += red[tid + s];
        __syncthreads();
    }
    if (tid == 0) g_fftsum[2 * mode + 1] = red[0];
}

// ---------------------------------------------------------------------------
// Fused tail kernel 2: copy v (all blocks) + scalars (block 0 / thread 0).
// ---------------------------------------------------------------------------
__global__ void finalize_out_kernel(float* __restrict__ out, int out_size) {
    int j = blockIdx.x * 128 + threadIdx.x;
    if (j < out_size) {
        if (j < NN) out[j] = g_v[j];
        else if (j >= NN + 11) out[j] = 0.f;
    }
    if (blockIdx.x == 0 && threadIdx.x == 0) {
        float res[11];
        res[0]  = sqrtf(g_msum[0]);
        res[1]  = g_msum[1] / (float)NN;
        res[2]  = g_msum[2] / (g_msum[3] + EPSF);
        res[3]  = g_msum[4] / (float)NN;
        res[4]  = g_msum[5] / (g_msum[6] + EPSF);
        res[5]  = g_msum[2] / (float)NN;
        res[6]  = g_msum[5] / (float)NN;
        res[7]  = g_fftsum[0] / 4097.0f;
        res[8]  = g_fftsum[1] / (g_fftsum[3] + EPSF);
        res[9]  = g_fftsum[4] / 4097.0f;
        res[10] = g_fftsum[5] / (g_fftsum[7] + EPSF);
        for (int k = 0; k < 11; k++)
            if (NN + k < out_size) out[NN + k] = res[k];
    }
}

extern "C" void kernel_launch(void* const* d_in, const int* in_sizes, int n_in,
                              void* d_out, int out_size) {
    const float* H = nullptr;
    const float* x = nullptr;
    const float* vt = nullptr;
    const float* qt = nullptr;
    int vecseen = 0;
    for (int i = 0; i < n_in; i++) {
        if (in_sizes[i] == NN * NN) {
            H = (const float*)d_in[i];
        } else if (in_sizes[i] == NN) {
            if (vecseen == 0)      x  = (const float*)d_in[i];
            else if (vecseen == 1) vt = (const float*)d_in[i];
            else if (vecseen == 2) qt = (const float*)d_in[i];
            vecseen++;
        }
    }
    float* out = (float*)d_out;

    cudaFuncSetAttribute(cgm_persistent, cudaFuncAttributeMaxDynamicSharedMemorySize,
                         SMEM_TOTAL);

    // fp32 H -> int16 per-row quantized copy (deterministic, each replay)
    quant_h_kernel<<<NN, 256>>>(H);

    cgm_persistent<<<NCTA, NTHR, SMEM_TOTAL>>>(x);
    metrics_fft_kernel<<<5, 1024>>>(x, qt, vt);
    {
        int nblk = (out_size + 127) / 128;
        if (nblk < 1) nblk = 1;
        finalize_out_kernel<<<nblk, 128>>>(out, out_size);
    }
}

// round 17
// speedup vs baseline: 1.2521x; 1.1002x over previous
#include <cuda_runtime.h>
#include <cstdint>
#include <math.h>

#define NN 8192
#define EPSF 1e-20f
#define NITER 32
#define NCTA 148
#define NTHR 512
#define ROWB 16384               // bytes per int16 H row
#define RDEPTH 8                 // TMA ring slots (power of 2)

// dynamic smem layout
#define SM_MBAR 0                // 8 mbarriers, 16B stride (ends 128)
#define SM_WRED 128              // 2 x 32 warp partials, pair-double-buffered
#define SM_GPART 1024            // 512 floats (phase-B group partials + reduce scratch)
#define SM_SRED 3072             // 64 floats (phase-B rs partials)
#define SM_T    3328             // 64 floats: this CTA's t_r = (Hp)_row
#define SM_QH   3584             // 64 floats: incremental q_hat for own rows
#define SM_P    3840             // 56 floats: p on own columns (for phaseB)
#define SM_SC   4096             // 64 floats: per-row quant scales
#define SM_RING 4352             // RDEPTH x 16384 row buffers
#define SMEM_TOTAL (SM_RING + RDEPTH * ROWB)

// ---- device scratch (no allocations allowed) ----
__device__ short g_Hq[(size_t)NN * NN];    // 134 MB int16 quantized H
__device__ float g_rowscale[NN];           // per-row scale (maxabs/32767)
__device__ float g_slab[NCTA * NN];        // per-CTA Ap / b partial slabs
__device__ float g_ttpart[NCTA];
__device__ float g_rspart[NCTA];
__device__ float g_r[NN], g_v[NN], g_qh[NN];
__device__ float g_msum[8];
__device__ float g_fftsum[8];
__device__ unsigned g_flags[NCTA];         // grid-barrier flags (monotone)

// row partition shared by quant_setup and persistent kernels:
// 100 CTAs x 56 rows + 48 CTAs x 54 rows = 8192 (even counts)
__device__ __forceinline__ void row_part(int bid, int& row0, int& nrows) {
    if (bid < 100) { row0 = bid * 56; nrows = 56; }
    else           { row0 = 5600 + (bid - 100) * 54; nrows = 54; }
}

// ---------------- PTX helpers ----------------
__device__ __forceinline__ uint32_t sm_u32(const void* p) {
    uint32_t a;
    asm("{ .reg .u64 t; cvta.to.shared.u64 t, %1; cvt.u32.u64 %0, t; }" : "=r"(a) : "l"(p));
    return a;
}
#define MB_INIT(a, c) \
    asm volatile("mbarrier.init.shared.b64 [%0], %1;" :: "r"(a), "r"(c) : "memory")
#define MB_EXPECT(a, b) \
    asm volatile("mbarrier.arrive.expect_tx.shared.b64 _, [%0], %1;" :: "r"(a), "r"(b) : "memory")
#define BULK_LD(dst, src, sz, mb) \
    asm volatile("cp.async.bulk.shared::cta.global.mbarrier::complete_tx::bytes [%0], [%1], %2, [%3];" \
                 :: "r"(dst), "l"(src), "r"(sz), "r"(mb) : "memory")

__device__ __forceinline__ void mb_wait(uint32_t mbar, uint32_t parity) {
    uint32_t done;
    do {
        asm volatile("{ .reg .pred p; mbarrier.try_wait.parity.acquire.cta.shared::cta.b64 p, [%1], %2; "
                     "selp.b32 %0, 1, 0, p; }" : "=r"(done) : "r"(mbar), "r"(parity) : "memory");
    } while (!done);
}

__device__ __forceinline__ void grid_bar(int tid, int bid, unsigned gen) {
    __syncthreads();
    if (tid == 0)
        asm volatile("st.global.release.gpu.u32 [%0], %1;" :: "l"(&g_flags[bid]), "r"(gen) : "memory");
    if (tid < NCTA) {
        unsigned v;
        do {
            asm volatile("ld.global.acquire.gpu.u32 %0, [%1];" : "=r"(v) : "l"(&g_flags[tid]) : "memory");
        } while ((int)(v - gen) < 0);
    }
    __syncthreads();
}

// deterministic 512-thread sum (fixed tree), result broadcast
__device__ __forceinline__ float block_sum512(float v, float* scr, int tid) {
    for (int o = 16; o; o >>= 1) v += __shfl_xor_sync(0xffffffffu, v, o);
    if ((tid & 31) == 0) scr[tid >> 5] = v;
    __syncthreads();
    if (tid < 16) {
        float w = scr[tid];
        for (int o = 8; o; o >>= 1) w += __shfl_xor_sync(0xffffu, w, o);
        if (tid == 0) scr[0] = w;
    }
    __syncthreads();
    float s = scr[0];
    __syncthreads();
    return s;
}

// int16 unpack helpers (R13-exact)
__device__ __forceinline__ void acc_dot8(uint4 raw, const float* pf, float& d) {
    const short* s = (const short*)&raw;
#pragma unroll
    for (int e = 0; e < 8; e++) d += (float)s[e] * pf[e];
}
__device__ __forceinline__ void acc_apa8(uint4 raw, float coef, float* ap) {
    const short* s = (const short*)&raw;
#pragma unroll
    for (int e = 0; e < 8; e++) ap[e] += coef * (float)s[e];
}

// quantize 4 floats of a float4 into packed int16 pair
__device__ __forceinline__ uint2 quant4(float4 f, float inv) {
    int q0 = max(-32767, min(32767, __float2int_rn(f.x * inv)));
    int q1 = max(-32767, min(32767, __float2int_rn(f.y * inv)));
    int q2 = max(-32767, min(32767, __float2int_rn(f.z * inv)));
    int q3 = max(-32767, min(32767, __float2int_rn(f.w * inv)));
    uint2 o;
    o.x = (unsigned)(unsigned short)(short)q0 | ((unsigned)(unsigned short)(short)q1 << 16);
    o.y = (unsigned)(unsigned short)(short)q2 | ((unsigned)(unsigned short)(short)q3 << 16);
    return o;
}

// ---------------------------------------------------------------------------
// Fused quantization + setup: 148 CTAs, same row/col partition as CG kernel.
// Per row: stage fp32 row (prefetch next before the max barrier), block-max,
// quantize -> g_Hq, and bacc += x[row] * row (fp32).  CTA writes its b-partial
// slab in the persistent kernel's slab layout; kernel boundary = grid barrier.
// Thread owns float4 indices 2t, 2t+1, 2t+1024, 2t+1025
// (= int16 uint4 indices t and 512+t).
// ---------------------------------------------------------------------------
__global__ __launch_bounds__(NTHR, 1) void quant_setup_kernel(const float* __restrict__ H,
                                                              const float* __restrict__ x) {
    __shared__ float red[2][16];
    int tid = threadIdx.x, bid = blockIdx.x;
    int row0, nrows;
    row_part(bid, row0, nrows);

    const int f0 = 2 * tid, f1 = 2 * tid + 1, f2 = 2 * tid + 1024, f3 = 2 * tid + 1025;
    float bacc[16];
#pragma unroll
    for (int i = 0; i < 16; i++) bacc[i] = 0.f;

    float4 cur[4];
    {
        const float4* h4 = (const float4*)(H + (size_t)row0 * NN);
        cur[0] = h4[f0]; cur[1] = h4[f1]; cur[2] = h4[f2]; cur[3] = h4[f3];
    }
    for (int r = 0; r < nrows; r++) {
        // prefetch next row (stays in flight across the reduce barrier)
        float4 nxt[4];
        if (r + 1 < nrows) {
            const float4* h4 = (const float4*)(H + (size_t)(row0 + r + 1) * NN);
            nxt[0] = h4[f0]; nxt[1] = h4[f1]; nxt[2] = h4[f2]; nxt[3] = h4[f3];
        }
        // local max
        float m = 0.f;
#pragma unroll
        for (int c = 0; c < 4; c++) {
            m = fmaxf(m, fmaxf(fmaxf(fabsf(cur[c].x), fabsf(cur[c].y)),
                               fmaxf(fabsf(cur[c].z), fabsf(cur[c].w))));
        }
        for (int o = 16; o; o >>= 1) m = fmaxf(m, __shfl_xor_sync(0xffffffffu, m, o));
        int buf = r & 1;
        if ((tid & 31) == 0) red[buf][tid >> 5] = m;
        __syncthreads();
        float maxab = red[buf][0];
#pragma unroll
        for (int w = 1; w < 16; w++) maxab = fmaxf(maxab, red[buf][w]);
        maxab = fmaxf(maxab, 1e-30f);
        if (tid == 0) g_rowscale[row0 + r] = maxab / 32767.0f;
        float inv = 32767.0f / maxab;
        // quantize + write
        uint2 qa = quant4(cur[0], inv), qb = quant4(cur[1], inv);
        uint2 qc = quant4(cur[2], inv), qd = quant4(cur[3], inv);
        uint4* dst = (uint4*)g_Hq + (size_t)(row0 + r) * 1024;
        dst[tid]       = make_uint4(qa.x, qa.y, qb.x, qb.y);
        dst[512 + tid] = make_uint4(qc.x, qc.y, qd.x, qd.y);
        // b accumulation in fp32
        float xr = x[row0 + r];
#pragma unroll
        for (int c = 0; c < 4; c++) {
            bacc[4 * c]     += xr * cur[c].x;
            bacc[4 * c + 1] += xr * cur[c].y;
            bacc[4 * c + 2] += xr * cur[c].z;
            bacc[4 * c + 3] += xr * cur[c].w;
        }
        if (r + 1 < nrows) {
#pragma unroll
            for (int c = 0; c < 4; c++) cur[c] = nxt[c];
        }
    }
    // write b-partial slab (persistent kernel's layout)
    float4* slab4 = (float4*)(g_slab + (size_t)bid * NN);
    const float4* a4 = (const float4*)bacc;
    slab4[f0] = a4[0];
    slab4[f1] = a4[1];
    slab4[f2] = a4[2];
    slab4[f3] = a4[3];
}

// ---------------------------------------------------------------------------
// CG matvec pass (R13-exact pairwise int16 TMA-ring loop — do not modify).
// pre_done: first RDEPTH loads already issued (cross-pass prefetch).
// pre_next: issue next pass's first RDEPTH loads before returning.
// ---------------------------------------------------------------------------
__device__ __forceinline__ float run_pass(char* smem, uint32_t smb, int tid,
                                          int row0, int nrows, unsigned& gq,
                                          const float* pf, float* apaf,
                                          const float* scsm,
                                          bool pre_done, bool pre_next) {
    float* wred = (float*)(smem + SM_WRED);
    float* smt  = (float*)(smem + SM_T);
    const short* Hb = g_Hq;
#pragma unroll
    for (int i = 0; i < 16; i++) apaf[i] = 0.f;
    float ta = 0.f;
    if (!pre_done && tid == 0) {
        for (int k = 0; k < RDEPTH; k++) {
            unsigned u = gq + k;
            uint32_t slot = u & (RDEPTH - 1);
            uint32_t mb = smb + SM_MBAR + slot * 16;
            MB_EXPECT(mb, ROWB);
            BULK_LD(smb + SM_RING + slot * ROWB,
                    (const void*)(Hb + (size_t)(row0 + k) * NN), (uint32_t)ROWB, mb);
        }
    }
    for (int r = 0; r < nrows; r += 2) {
        unsigned u0 = gq + r, u1 = u0 + 1;
        uint32_t slot0 = u0 & (RDEPTH - 1), slot1 = u1 & (RDEPTH - 1);
        mb_wait(smb + SM_MBAR + slot0 * 16, (u0 >> 3) & 1);
        mb_wait(smb + SM_MBAR + slot1 * 16, (u1 >> 3) & 1);
        const uint4* ra = (const uint4*)(smem + SM_RING + slot0 * ROWB);
        const uint4* rb = (const uint4*)(smem + SM_RING + slot1 * ROWB);
        uint4 a0 = ra[tid], a1 = ra[tid + 512];
        uint4 b0 = rb[tid], b1 = rb[tid + 512];
        float d0 = 0.f, d1 = 0.f;
        acc_dot8(a0, pf, d0);
        acc_dot8(b0, pf, d1);
        acc_dot8(a1, pf + 8, d0);
        acc_dot8(b1, pf + 8, d1);
#pragma unroll
        for (int o = 16; o; o >>= 1) {
            d0 += __shfl_xor_sync(0xffffffffu, d0, o);
            d1 += __shfl_xor_sync(0xffffffffu, d1, o);
        }
        int buf = (r >> 1) & 1;
        if ((tid & 31) == 0) {
            wred[buf * 32 + (tid >> 5)] = d0;
            wred[buf * 32 + 16 + (tid >> 5)] = d1;
        }
        __syncthreads();
        if (tid == 0 && r + RDEPTH < nrows) {
            uint32_t mb0 = smb + SM_MBAR + slot0 * 16;
            MB_EXPECT(mb0, ROWB);
            BULK_LD(smb + SM_RING + slot0 * ROWB,
                    (const void*)(Hb + (size_t)(row0 + r + RDEPTH) * NN), (uint32_t)ROWB, mb0);
            uint32_t mb1 = smb + SM_MBAR + slot1 * 16;
            MB_EXPECT(mb1, ROWB);
            BULK_LD(smb + SM_RING + slot1 * ROWB,
                    (const void*)(Hb + (size_t)(row0 + r + 1 + RDEPTH) * NN), (uint32_t)ROWB, mb1);
        }
        float t0 = 0.f, t1 = 0.f;
#pragma unroll
        for (int w = 0; w < 16; w++) {
            t0 += wred[buf * 32 + w];
            t1 += wred[buf * 32 + 16 + w];
        }
        float s0 = scsm[r], s1 = scsm[r + 1];
        float tr0 = t0 * s0, tr1 = t1 * s1;
        if (tid == 0) { smt[r] = tr0; smt[r + 1] = tr1; }
        ta += tr0 * tr0 + tr1 * tr1;
        float c0 = tr0 * s0, c1 = tr1 * s1;
        acc_apa8(a0, c0, apaf);
        acc_apa8(b0, c1, apaf);
        acc_apa8(a1, c0, apaf + 8);
        acc_apa8(b1, c1, apaf + 8);
    }
    gq += (unsigned)nrows;
    if (pre_next && tid == 0) {
        for (int k = 0; k < RDEPTH; k++) {
            unsigned u = gq + k;
            uint32_t slot = u & (RDEPTH - 1);
            uint32_t mb = smb + SM_MBAR + slot * 16;
            MB_EXPECT(mb, ROWB);
            BULK_LD(smb + SM_RING + slot * ROWB,
                    (const void*)(Hb + (size_t)(row0 + k) * NN), (uint32_t)ROWB, mb);
        }
    }
    return ta;
}

// write apaf (16 cols per thread) to this CTA's slab
__device__ __forceinline__ void slab_store(int bid, int tid, const float* apaf) {
    float4* slab4 = (float4*)(g_slab + (size_t)bid * NN);
    const float4* a4 = (const float4*)apaf;
    slab4[2 * tid]        = a4[0];
    slab4[2 * tid + 1]    = a4[1];
    slab4[2 * tid + 1024] = a4[2];
    slab4[2 * tid + 1025] = a4[3];
}

// phase B: slab reduce over own columns + vector update (or setup init)
__device__ __forceinline__ void phaseB(char* smem, int tid, int bid, int c0, int nc,
                                       float alpha, bool setup) {
    float* sgp = (float*)(smem + SM_GPART);
    float* sred = (float*)(smem + SM_SRED);
    float* psm = (float*)(smem + SM_P);
    int g = tid >> 6, tc = tid & 63;
    float part = 0.f;
    if (tc < nc) {
#pragma unroll 4
        for (int cs = g; cs < NCTA; cs += 8) part += g_slab[(size_t)cs * NN + c0 + tc];
    }
    sgp[g * 64 + tc] = part;
    __syncthreads();
    if (tid < nc) {
        float ap = 0.f;
#pragma unroll
        for (int gg = 0; gg < 8; gg++) ap += sgp[gg * 64 + tid];
        int j = c0 + tid;
        float rn;
        if (setup) {
            g_v[j] = 0.f;
            g_r[j] = ap;      // r = b
            rn = ap;
        } else {
            g_v[j] += alpha * psm[tid];
            rn = g_r[j] - alpha * ap;
            g_r[j] = rn;
        }
        sred[tid] = rn * rn;
    }
    __syncthreads();
    if (tid == 0) {
        float s = 0.f;
        for (int i = 0; i < nc; i++) s += sred[i];
        g_rspart[bid] = s;
    }
}

// ---------------------------------------------------------------------------
// Persistent CG kernel: setup-init (slabs from quant_setup) + 32 iterations.
// ---------------------------------------------------------------------------
__global__ void __launch_bounds__(NTHR, 1) cgm_persistent() {
    extern __shared__ char smem[];
    int tid = threadIdx.x, bid = blockIdx.x;
    uint32_t smb = sm_u32(smem);
    float* smt = (float*)(smem + SM_T);
    float* smqh = (float*)(smem + SM_QH);
    float* psm = (float*)(smem + SM_P);
    float* scsm = (float*)(smem + SM_SC);
    float* scr = (float*)(smem + SM_GPART);
    if (tid == 0) {
        for (int s = 0; s < RDEPTH; s++) MB_INIT(smb + SM_MBAR + s * 16, 1);
    }
    if (tid < 64) smqh[tid] = 0.f;

    int row0, nrows;
    row_part(bid, row0, nrows);
    int c0 = row0, nc = nrows;

    if (tid < nrows) scsm[tid] = g_rowscale[row0 + tid];
    __syncthreads();
    unsigned base_gen = g_flags[bid];
    unsigned barn = 0;
    unsigned gq = 0;

    float apaf[16], pfv[16];
    float rs = 0.f;

    // ---- setup init: b-slabs already written by quant_setup_kernel ----
    phaseB(smem, tid, bid, c0, nc, 0.f, true);
    grid_bar(tid, bid, base_gen + (++barn));

    const int fidx[4] = { 2 * tid, 2 * tid + 1, 2 * tid + 1024, 2 * tid + 1025 };

    for (int it = 0; it < NITER; it++) {
        // ---- A: beta (parallel reduce), p update (regs + own-col smem) ----
        float rsv = (tid < NCTA) ? g_rspart[tid] : 0.f;
        float rs_new = block_sum512(rsv, scr, tid);
        float beta = (it == 0) ? 0.f : rs_new / (rs + EPSF);
        rs = rs_new;
#pragma unroll
        for (int c = 0; c < 4; c++) {
            float4 rr = ((const float4*)g_r)[fidx[c]];
            float4 pv;
            if (it == 0) pv = rr;
            else pv = make_float4(rr.x + beta * pfv[4 * c],     rr.y + beta * pfv[4 * c + 1],
                                  rr.z + beta * pfv[4 * c + 2], rr.w + beta * pfv[4 * c + 3]);
            pfv[4 * c] = pv.x; pfv[4 * c + 1] = pv.y;
            pfv[4 * c + 2] = pv.z; pfv[4 * c + 3] = pv.w;
            int col0 = 4 * fidx[c];
            if (col0 + 3 >= c0 && col0 < c0 + nc) {
#pragma unroll
                for (int e = 0; e < 4; e++) {
                    int jj = col0 + e;
                    if (jj >= c0 && jj < c0 + nc) psm[jj - c0] = pfv[4 * c + e];
                }
            }
        }
        __syncthreads();   // psm visible before pass
        // ---- matvec: slab partials of H^T(Hp), tt partials, smem t ----
        float ta = run_pass(smem, smb, tid, row0, nrows, gq, pfv, apaf,
                            scsm, it > 0, it < NITER - 1);
        slab_store(bid, tid, apaf);
        if (tid == 0) g_ttpart[bid] = ta;
        grid_bar(tid, bid, base_gen + (++barn));

        // ---- B: alpha (parallel reduce), qh += alpha*t, Ap reduce + v,r + rs ----
        float ttv = (tid < NCTA) ? g_ttpart[tid] : 0.f;
        float tt = block_sum512(ttv, scr, tid);
        float alpha = rs / (tt + EPSF);
        if (tid < nrows) smqh[tid] += alpha * smt[tid];
        __syncthreads();                 // scr reuse in phaseB
        phaseB(smem, tid, bid, c0, nc, alpha, false);
        grid_bar(tid, bid, base_gen + (++barn));
    }

    if (tid < nrows) g_qh[row0 + tid] = smqh[tid];
}

// ---------------------------------------------------------------------------
// Fused tail kernel 1: blocks 0-3 = FFT modes; block 4 = time-domain metrics.
// ---------------------------------------------------------------------------
__global__ void __launch_bounds__(1024) metrics_fft_kernel(const float* __restrict__ x,
                                                           const float* __restrict__ qt,
                                                           const float* __restrict__ vt) {
    int tid = threadIdx.x;
    if (blockIdx.x == 4) {
        float acc[7] = {0.f, 0.f, 0.f, 0.f, 0.f, 0.f, 0.f};
        for (int j = tid; j < NN; j += 1024) {
            float qh = g_qh[j], vv = g_v[j];
            float qtj = qt[j], vtj = vt[j];
            float d0 = qh - x[j];
            float d1 = qh - qtj;
            float d2 = vv - vtj;
            acc[0] += d0 * d0;
            acc[1] += fabsf(d1);
            acc[2] += d1 * d1;
            acc[3] += qtj * qtj;
            acc[4] += fabsf(d2);
            acc[5] += d2 * d2;
            acc[6] += vtj * vtj;
        }
        __shared__ float red[1024];
#pragma unroll
        for (int s = 0; s < 7; s++) {
            red[tid] = acc[s];
            __syncthreads();
            for (int o = 512; o > 0; o >>= 1) {
                if (tid < o) red[tid] += red[tid + o];
                __syncthreads();
            }
            if (tid == 0) g_msum[s] = red[0];
            __syncthreads();
        }
        return;
    }

    __shared__ float2 Z[4096];
    __shared__ float red[1024];
    int mode = blockIdx.x;

    for (int n = tid; n < 4096; n += 1024) {
        int i0 = 2 * n, i1 = 2 * n + 1;
        float a, b;
        if (mode == 0)      { a = g_qh[i0] - qt[i0]; b = g_qh[i1] - qt[i1]; }
        else if (mode == 1) { a = qt[i0];            b = qt[i1]; }
        else if (mode == 2) { a = g_v[i0] - vt[i0];  b = g_v[i1] - vt[i1]; }
        else                { a = vt[i0];            b = vt[i1]; }
        int r = (int)(__brev((unsigned)n) >> 20);
        Z[r] = make_float2(a, b);
    }
    __syncthreads();

    for (int half = 1; half < 4096; half <<= 1) {
        for (int i = tid; i < 2048; i += 1024) {
            int pos = i & (half - 1);
            int idx1 = ((i ^ pos) << 1) | pos;
            int idx2 = idx1 + half;
            float s, c;
            sincospif((float)pos / (float)half, &s, &c);
            float2 z2 = Z[idx2];
            float2 t = make_float2(c * z2.x + s * z2.y, c * z2.y - s * z2.x);
            float2 z1 = Z[idx1];
            Z[idx2] = make_float2(z1.x - t.x, z1.y - t.y);
            Z[idx1] = make_float2(z1.x + t.x, z1.y + t.y);
        }
        __syncthreads();
    }

    float sabs = 0.f, ssq = 0.f;
    for (int k = tid; k <= 4096; k += 1024) {
        float2 Zk = Z[k & 4095];
        float2 Zm = Z[(4096 - k) & 4095];
        float2 Zmc = make_float2(Zm.x, -Zm.y);
        float2 Fe = make_float2(0.5f * (Zk.x + Zmc.x), 0.5f * (Zk.y + Zmc.y));
        float2 Fd = make_float2(Zk.x - Zmc.x, Zk.y - Zmc.y);
        float2 Fo = make_float2(0.5f * Fd.y, -0.5f * Fd.x);
        float s, c;
        sincospif((float)k / 4096.0f, &s, &c);
        float Xr = Fe.x + (c * Fo.x + s * Fo.y);
        float Xi = Fe.y + (c * Fo.y - s * Fo.x);
        float m2 = Xr * Xr + Xi * Xi;
        sabs += sqrtf(m2);
        ssq += m2;
    }
    red[tid] = sabs;
    __syncthreads();
    for (int s = 512; s > 0; s >>= 1) {
        if (tid < s) red[tid] += red[tid + s];
        __syncthreads();
    }
    if (tid == 0) g_fftsum[2 * mode] = red[0];
    __syncthreads();
    red[tid] = ssq;
    __syncthreads();
    for (int s = 512; s > 0; s >>= 1) {
        if (tid < s) red[tid] += red[tid + s];
        __syncthreads();
    }
    if (tid == 0) g_fftsum[2 * mode + 1] = red[0];
}

// ---------------------------------------------------------------------------
// Fused tail kernel 2: copy v (all blocks) + scalars (block 0 / thread 0).
// ---------------------------------------------------------------------------
__global__ void finalize_out_kernel(float* __restrict__ out, int out_size) {
    int j = blockIdx.x * 128 + threadIdx.x;
    if (j < out_size) {
        if (j < NN) out[j] = g_v[j];
        else if (j >= NN + 11) out[j] = 0.f;
    }
    if (blockIdx.x == 0 && threadIdx.x == 0) {
        float res[11];
        res[0]  = sqrtf(g_msum[0]);
        res[1]  = g_msum[1] / (float)NN;
        res[2]  = g_msum[2] / (g_msum[3] + EPSF);
        res[3]  = g_msum[4] / (float)NN;
        res[4]  = g_msum[5] / (g_msum[6] + EPSF);
        res[5]  = g_msum[2] / (float)NN;
        res[6]  = g_msum[5] / (float)NN;
        res[7]  = g_fftsum[0] / 4097.0f;
        res[8]  = g_fftsum[1] / (g_fftsum[3] + EPSF);
        res[9]  = g_fftsum[4] / 4097.0f;
        res[10] = g_fftsum[5] / (g_fftsum[7] + EPSF);
        for (int k = 0; k < 11; k++)
            if (NN + k < out_size) out[NN + k] = res[k];
    }
}

extern "C" void kernel_launch(void* const* d_in, const int* in_sizes, int n_in,
                              void* d_out, int out_size) {
    const float* H = nullptr;
    const float* x = nullptr;
    const float* vt = nullptr;
    const float* qt = nullptr;
    int vecseen = 0;
    for (int i = 0; i < n_in; i++) {
        if (in_sizes[i] == NN * NN) {
            H = (const float*)d_in[i];
        } else if (in_sizes[i] == NN) {
            if (vecseen == 0)      x  = (const float*)d_in[i];
            else if (vecseen == 1) vt = (const float*)d_in[i];
            else if (vecseen == 2) qt = (const float*)d_in[i];
            vecseen++;
        }
    }
    float* out = (float*)d_out;

    cudaFuncSetAttribute(cgm_persistent, cudaFuncAttributeMaxDynamicSharedMemorySize,
                         SMEM_TOTAL);

    // fused: quantize H to int16 AND compute b = H^T x partial slabs
    quant_setup_kernel<<<NCTA, NTHR>>>(H, x);

    cgm_persistent<<<NCTA, NTHR, SMEM_TOTAL>>>();
    metrics_fft_kernel<<<5, 1024>>>(x, qt, vt);
    {
        int nblk = (out_size + 127) / 128;
        if (nblk < 1) nblk = 1;
        finalize_out_kernel<<<nblk, 128>>>(out, out_size);
    }
}